// round 1
// baseline (speedup 1.0000x reference)
#include <cuda_runtime.h>
#include <cuda_bf16.h>
#include <cstdint>
#include <cstdio>

#define B_      1024
#define K_      11
#define L_KIN_  128
#define L_SUB_  64
#define L_STR_  128
#define D_SEQ_  1280
#define D_STR_  512
#define EMB_    1792        // D_SEQ + D_STR
#define EMB2_   2564        // 2*D_SEQ + 4
#define M_      (B_ * K_)   // 11264
#define NCHUNK_ 44          // 11264 / 44 = 256 rows per chunk

// ---------------- scratch (device globals; no runtime allocation) ----------------
__device__ float g_X [(size_t)M_ * EMB2_];   // gfeat (stride EMB_), later gfeat2 (stride EMB2_)
__device__ float g_Y [(size_t)M_ * EMB2_];   // H (stride EMB_), later H2 (stride EMB2_)
__device__ float g_P1[(size_t)M_ * D_SEQ_];  // F1, later G1
__device__ float g_P2[(size_t)M_ * D_SEQ_];  // F2, later G2
__device__ float g_kin[(size_t)B_ * D_SEQ_];
__device__ float g_psum[NCHUNK_ * EMB2_];
__device__ float g_psq [NCHUNK_ * EMB2_];
__device__ float g_ss  [8 * EMB2_];          // sA,tA,sB,tB per stage

// RES_PROPS table: order G A S P V T C I L N D Q K E M H F R Y W X
__constant__ float c_props[21 * 4] = {
    0,0,0,0,  // G
    1,0,0,0,  // A
    0,0,0,0,  // S
    0,0,0,0,  // P
    1,0,0,0,  // V
    0,0,0,0,  // T
    0,0,0,0,  // C
    1,0,0,0,  // I
    1,0,0,0,  // L
    0,0,0,0,  // N
    0,0,1,0,  // D
    0,0,0,0,  // Q
    0,0,0,1,  // K
    0,0,1,0,  // E
    1,0,0,0,  // M
    0,0,0,1,  // H
    0,1,0,0,  // F
    0,0,0,1,  // R
    0,1,0,0,  // Y
    0,1,0,0,  // W
    0,0,0,0   // X
};

__device__ __forceinline__ float tf32r(float x) {
    unsigned u;
    asm("cvt.rna.tf32.f32 %0, %1;" : "=r"(u) : "f"(x));
    return __uint_as_float(u);
}

__device__ __forceinline__ float sigmoidf_(float x) {
    return 1.f / (1.f + expf(-x));
}

__device__ __forceinline__ void mma_tf32(float* d, const unsigned* a, const unsigned* b) {
    asm volatile(
        "mma.sync.aligned.m16n8k8.row.col.f32.tf32.tf32.f32 "
        "{%0,%1,%2,%3}, {%4,%5,%6,%7}, {%8,%9}, {%0,%1,%2,%3};\n"
        : "+f"(d[0]), "+f"(d[1]), "+f"(d[2]), "+f"(d[3])
        : "r"(a[0]), "r"(a[1]), "r"(a[2]), "r"(a[3]), "r"(b[0]), "r"(b[1]));
}

// ---------------- kernel 1: kin mean over rows 1..127 ----------------
__global__ __launch_bounds__(256) void kin_mean_kernel(const float* __restrict__ kin_in,
                                                       float* __restrict__ kin_out) {
    int b = blockIdx.x;
    const float* base = kin_in + ((size_t)b * L_KIN_ + 1) * D_SEQ_;
    for (int i = threadIdx.x; i < D_SEQ_ / 4; i += blockDim.x) {
        float4 acc = make_float4(0.f, 0.f, 0.f, 0.f);
        for (int r = 0; r < L_KIN_ - 1; ++r) {
            float4 v = *(const float4*)(base + (size_t)r * D_SEQ_ + i * 4);
            acc.x += v.x; acc.y += v.y; acc.z += v.z; acc.w += v.w;
        }
        const float inv = 1.f / 127.f;
        float4 o = make_float4(acc.x * inv, acc.y * inv, acc.z * inv, acc.w * inv);
        *(float4*)(kin_out + (size_t)b * D_SEQ_ + i * 4) = o;
    }
}

// ---------------- kernel 2: build gfeat + node_feature output ----------------
__global__ __launch_bounds__(256) void build_gfeat_kernel(
    const float* __restrict__ sub, const float* __restrict__ n2,
    const float* __restrict__ phos, const int* __restrict__ position,
    float* __restrict__ X, float* __restrict__ node_feature) {
    int b = blockIdx.x, k = blockIdx.y;
    size_t m = (size_t)b * K_ + k;
    const float* src1 = sub + ((size_t)b * L_SUB_ + 1 + k) * D_SEQ_;
    float* dst = X + m * EMB_;
    float* nf  = node_feature + m * D_SEQ_;
    bool mid = (k == K_ / 2);
    for (int i = threadIdx.x; i < D_SEQ_ / 4; i += blockDim.x) {
        float4 v = *(const float4*)(src1 + i * 4);
        *(float4*)(nf + i * 4) = v;
        if (mid) {
            float4 p = *(const float4*)(phos + i * 4);
            v.x += p.x; v.y += p.y; v.z += p.z; v.w += p.w;
        }
        *(float4*)(dst + i * 4) = v;
    }
    int row = position[b] + k - K_ / 2;
    bool ok = (row >= 0 && row < L_STR_);
    const float* src2 = n2 + ((size_t)b * L_STR_ + (ok ? row : 0)) * D_STR_;
    for (int i = threadIdx.x; i < D_STR_ / 4; i += blockDim.x) {
        float4 v = make_float4(0.f, 0.f, 0.f, 0.f);
        if (ok) v = *(const float4*)(src2 + i * 4);
        if (mid) {
            float4 p = *(const float4*)(phos + D_SEQ_ + i * 4);
            v.x += p.x; v.y += p.y; v.z += p.z; v.w += p.w;
        }
        *(float4*)(dst + D_SEQ_ + i * 4) = v;
    }
}

// ---------------- column statistics (two-pass, deterministic) ----------------
__global__ __launch_bounds__(256) void colstats_partial(
    const float* __restrict__ X, float* __restrict__ psum, float* __restrict__ psq,
    int ncols, int rows_per_chunk) {
    int col = blockIdx.x * blockDim.x + threadIdx.x;
    if (col >= ncols) return;
    int r0 = blockIdx.y * rows_per_chunk;
    float s = 0.f, q = 0.f;
    const float* p = X + (size_t)r0 * ncols + col;
    for (int r = 0; r < rows_per_chunk; ++r, p += ncols) {
        float v = *p;
        s += v; q += v * v;
    }
    psum[blockIdx.y * ncols + col] = s;
    psq [blockIdx.y * ncols + col] = q;
}

__global__ __launch_bounds__(256) void finalize_stats(
    const float* __restrict__ psum, const float* __restrict__ psq, int ncols,
    const float* __restrict__ gA, const float* __restrict__ bA,
    const float* __restrict__ gB, const float* __restrict__ bB,
    float* __restrict__ sA, float* __restrict__ tA,
    float* __restrict__ sB, float* __restrict__ tB) {
    int col = blockIdx.x * blockDim.x + threadIdx.x;
    if (col >= ncols) return;
    float s = 0.f, q = 0.f;
    for (int c = 0; c < NCHUNK_; ++c) {
        s += psum[c * ncols + col];
        q += psq [c * ncols + col];
    }
    const float inv_n = 1.f / (float)M_;
    float mean = s * inv_n;
    float var  = q * inv_n - mean * mean;
    float inv  = rsqrtf(var + 1e-5f);
    float sa = gA[col] * inv; sA[col] = sa; tA[col] = bA[col] - mean * sa;
    float sb = gB[col] * inv; sB[col] = sb; tB[col] = bB[col] - mean * sb;
}

// ---------------- tf32 GEMM with fused pre-activation ----------------
// C[M,N] = pre(A)[M,Kd] @ W[Kd,N] + bias
// mode 0: pre(x) = relu(x*s[k]+t[k]);  mode 1: pre(x) = relu(x)
__global__ __launch_bounds__(256) void gemm_tf32(
    const float* __restrict__ A, const float* __restrict__ W,
    const float* __restrict__ s, const float* __restrict__ t,
    const float* __restrict__ bias, float* __restrict__ C,
    int Kd, int N, int mode) {
    __shared__ float As[128][20];   // padded: conflict-free frag loads, 16B-aligned rows
    __shared__ float Bs[16][136];

    const int tid  = threadIdx.x;
    const int bm   = blockIdx.y * 128;
    const int bn   = blockIdx.x * 128;
    const int warp = tid >> 5, lane = tid & 31;
    const int wm = (warp >> 2) << 6;   // 0,64
    const int wn = (warp & 3) << 5;    // 0,32,64,96
    const int g  = lane >> 2, tg = lane & 3;

    float acc[4][4][4];
    #pragma unroll
    for (int mt = 0; mt < 4; ++mt)
        #pragma unroll
        for (int nt = 0; nt < 4; ++nt)
            #pragma unroll
            for (int i = 0; i < 4; ++i) acc[mt][nt][i] = 0.f;

    const int ktiles = (Kd + 15) >> 4;
    for (int kt = 0; kt < ktiles; ++kt) {
        const int k0 = kt << 4;
        // A tile: 128 x 16
        #pragma unroll
        for (int j = 0; j < 2; ++j) {
            int f   = tid + (j << 8);
            int row = f >> 2;
            int c4  = (f & 3) << 2;
            int gk  = k0 + c4;
            float4 v = make_float4(0.f, 0.f, 0.f, 0.f);
            if (gk < Kd) {   // Kd % 4 == 0 so float4 granularity is exact
                v = *(const float4*)(A + (size_t)(bm + row) * Kd + gk);
                if (mode == 0) {
                    v.x = fmaxf(fmaf(v.x, s[gk],     t[gk]),     0.f);
                    v.y = fmaxf(fmaf(v.y, s[gk + 1], t[gk + 1]), 0.f);
                    v.z = fmaxf(fmaf(v.z, s[gk + 2], t[gk + 2]), 0.f);
                    v.w = fmaxf(fmaf(v.w, s[gk + 3], t[gk + 3]), 0.f);
                } else {
                    v.x = fmaxf(v.x, 0.f); v.y = fmaxf(v.y, 0.f);
                    v.z = fmaxf(v.z, 0.f); v.w = fmaxf(v.w, 0.f);
                }
                v.x = tf32r(v.x); v.y = tf32r(v.y); v.z = tf32r(v.z); v.w = tf32r(v.w);
            }
            *(float4*)&As[row][c4] = v;
        }
        // B tile: 16 x 128
        #pragma unroll
        for (int j = 0; j < 2; ++j) {
            int f   = tid + (j << 8);
            int row = f >> 5;
            int c4  = (f & 31) << 2;
            int gk  = k0 + row;
            int gn  = bn + c4;
            float4 v = make_float4(0.f, 0.f, 0.f, 0.f);
            if (gk < Kd && gn < N) {   // N % 4 == 0
                v = *(const float4*)(W + (size_t)gk * N + gn);
                v.x = tf32r(v.x); v.y = tf32r(v.y); v.z = tf32r(v.z); v.w = tf32r(v.w);
            }
            *(float4*)&Bs[row][c4] = v;
        }
        __syncthreads();

        #pragma unroll
        for (int kk = 0; kk < 2; ++kk) {
            const int kb = kk << 3;
            unsigned af[4][4], bf[4][2];
            #pragma unroll
            for (int mt = 0; mt < 4; ++mt) {
                int r = wm + (mt << 4);
                af[mt][0] = __float_as_uint(As[r + g][kb + tg]);
                af[mt][1] = __float_as_uint(As[r + g + 8][kb + tg]);
                af[mt][2] = __float_as_uint(As[r + g][kb + tg + 4]);
                af[mt][3] = __float_as_uint(As[r + g + 8][kb + tg + 4]);
            }
            #pragma unroll
            for (int nt = 0; nt < 4; ++nt) {
                int c = wn + (nt << 3) + g;
                bf[nt][0] = __float_as_uint(Bs[kb + tg][c]);
                bf[nt][1] = __float_as_uint(Bs[kb + tg + 4][c]);
            }
            #pragma unroll
            for (int mt = 0; mt < 4; ++mt)
                #pragma unroll
                for (int nt = 0; nt < 4; ++nt)
                    mma_tf32(acc[mt][nt], af[mt], bf[nt]);
        }
        __syncthreads();
    }

    // epilogue: += bias, store
    #pragma unroll
    for (int mt = 0; mt < 4; ++mt) {
        int r = bm + wm + (mt << 4);
        #pragma unroll
        for (int nt = 0; nt < 4; ++nt) {
            int c = bn + wn + (nt << 3) + (tg << 1);
            if (c < N) {   // N even, so c+1 < N too
                float b0 = bias[c], b1 = bias[c + 1];
                C[(size_t)(r + g) * N + c]         = acc[mt][nt][0] + b0;
                C[(size_t)(r + g) * N + c + 1]     = acc[mt][nt][1] + b1;
                C[(size_t)(r + g + 8) * N + c]     = acc[mt][nt][2] + b0;
                C[(size_t)(r + g + 8) * N + c + 1] = acc[mt][nt][3] + b1;
            }
        }
    }
}

// ---------------- combine stage 1 -> build gfeat2 ----------------
__global__ __launch_bounds__(256) void combine1_kernel(
    const float* __restrict__ F1, const float* __restrict__ F2,
    const float* __restrict__ nf, const float* __restrict__ kin,
    const float* __restrict__ a, const int* __restrict__ raw_seq,
    float* __restrict__ X2) {
    int b = blockIdx.x, k = blockIdx.y;
    size_t m = (size_t)b * K_ + k;
    float a0 = a[0], a1 = a[1];
    const float* f1 = F1 + m * D_SEQ_;
    const float* f2 = F2 + m * D_SEQ_;
    const float* g1 = nf + m * D_SEQ_;
    const float* kb = kin + (size_t)b * D_SEQ_;
    float* dst = X2 + m * EMB2_;
    for (int i = threadIdx.x; i < D_SEQ_ / 4; i += blockDim.x) {
        float4 v1 = *(const float4*)(f1 + i * 4);
        float4 v2 = *(const float4*)(f2 + i * 4);
        float4 vg = *(const float4*)(g1 + i * 4);
        float4 r;
        r.x = sigmoidf_(v1.x) * vg.x * a0 + v2.x * a1;
        r.y = sigmoidf_(v1.y) * vg.y * a0 + v2.y * a1;
        r.z = sigmoidf_(v1.z) * vg.z * a0 + v2.z * a1;
        r.w = sigmoidf_(v1.w) * vg.w * a0 + v2.w * a1;
        *(float4*)(dst + i * 4) = r;
        *(float4*)(dst + D_SEQ_ + i * 4) = *(const float4*)(kb + i * 4);
    }
    if (threadIdx.x < 4) {
        int sid = raw_seq[m];
        dst[2 * D_SEQ_ + threadIdx.x] = c_props[sid * 4 + threadIdx.x];
    }
}

// ---------------- final combine + reduce over K ----------------
__global__ __launch_bounds__(256) void final_kernel(
    const float* __restrict__ G1, const float* __restrict__ G2,
    const float* __restrict__ X2, const float* __restrict__ a2,
    float* __restrict__ out) {
    int b = blockIdx.x;
    float s0 = a2[0], s1 = a2[1];
    for (int i = threadIdx.x; i < D_SEQ_ / 4; i += blockDim.x) {
        float4 acc = make_float4(0.f, 0.f, 0.f, 0.f);
        for (int k = 0; k < K_; ++k) {
            size_t m = (size_t)b * K_ + k;
            float4 f1 = *(const float4*)(G1 + m * D_SEQ_ + i * 4);
            float4 f2 = *(const float4*)(G2 + m * D_SEQ_ + i * 4);
            float4 gn = *(const float4*)(X2 + m * EMB2_ + i * 4);
            acc.x += sigmoidf_(f1.x) * gn.x * s0 + f2.x * s1;
            acc.y += sigmoidf_(f1.y) * gn.y * s0 + f2.y * s1;
            acc.z += sigmoidf_(f1.z) * gn.z * s0 + f2.z * s1;
            acc.w += sigmoidf_(f1.w) * gn.w * s0 + f2.w * s1;
        }
        *(float4*)(out + (size_t)b * D_SEQ_ + i * 4) = acc;
    }
}

// ---------------- launch ----------------
extern "C" void kernel_launch(void* const* d_in, const int* in_sizes, int n_in,
                              void* d_out, int out_size) {
    const float* kin_in   = (const float*)d_in[0];
    const float* sub      = (const float*)d_in[1];
    const float* n2       = (const float*)d_in[2];
    // d_in[3] = plddt (unused by reference)
    const float* a        = (const float*)d_in[4];
    const float* a2       = (const float*)d_in[5];
    const float* phos     = (const float*)d_in[6];
    const float* g1_gamma = (const float*)d_in[7];
    const float* g1_beta  = (const float*)d_in[8];
    const float* g1_W     = (const float*)d_in[9];
    const float* g1_b     = (const float*)d_in[10];
    const float* r1_gamma = (const float*)d_in[11];
    const float* r1_beta  = (const float*)d_in[12];
    const float* r1_W1    = (const float*)d_in[13];
    const float* r1_b1    = (const float*)d_in[14];
    const float* r1_W2    = (const float*)d_in[15];
    const float* r1_b2    = (const float*)d_in[16];
    const float* g2_gamma = (const float*)d_in[17];
    const float* g2_beta  = (const float*)d_in[18];
    const float* g2_W     = (const float*)d_in[19];
    const float* g2_b     = (const float*)d_in[20];
    const float* r2_gamma = (const float*)d_in[21];
    const float* r2_beta  = (const float*)d_in[22];
    const float* r2_W1    = (const float*)d_in[23];
    const float* r2_b1    = (const float*)d_in[24];
    const float* r2_W2    = (const float*)d_in[25];
    const float* r2_b2    = (const float*)d_in[26];
    const int*   position = (const int*)d_in[27];
    const int*   raw_seq  = (const int*)d_in[28];

    float* out = (float*)d_out;
    float* graph_feature = out;                             // (B, D_SEQ)
    float* node_feature  = out + (size_t)B_ * D_SEQ_;       // (B, K, D_SEQ)

    float *X, *Y, *P1, *P2, *kin, *psum, *psq, *ss;
    cudaGetSymbolAddress((void**)&X,    g_X);
    cudaGetSymbolAddress((void**)&Y,    g_Y);
    cudaGetSymbolAddress((void**)&P1,   g_P1);
    cudaGetSymbolAddress((void**)&P2,   g_P2);
    cudaGetSymbolAddress((void**)&kin,  g_kin);
    cudaGetSymbolAddress((void**)&psum, g_psum);
    cudaGetSymbolAddress((void**)&psq,  g_psq);
    cudaGetSymbolAddress((void**)&ss,   g_ss);

    float* s_g1 = ss + 0 * EMB2_;
    float* t_g1 = ss + 1 * EMB2_;
    float* s_r1 = ss + 2 * EMB2_;
    float* t_r1 = ss + 3 * EMB2_;
    float* s_g2 = ss + 4 * EMB2_;
    float* t_g2 = ss + 5 * EMB2_;
    float* s_r2 = ss + 6 * EMB2_;
    float* t_r2 = ss + 7 * EMB2_;

    // 1. kin mean
    kin_mean_kernel<<<B_, 256>>>(kin_in, kin);

    // 2. build gfeat (into X, stride EMB_) + node_feature output
    build_gfeat_kernel<<<dim3(B_, K_), 256>>>(sub, n2, phos, position, X, node_feature);

    // 3-4. BN stats for stage 1
    colstats_partial<<<dim3((EMB_ + 255) / 256, NCHUNK_), 256>>>(X, psum, psq, EMB_, M_ / NCHUNK_);
    finalize_stats<<<(EMB_ + 255) / 256, 256>>>(psum, psq, EMB_,
        g1_gamma, g1_beta, r1_gamma, r1_beta, s_g1, t_g1, s_r1, t_r1);

    // 5-7. stage-1 GEMMs
    gemm_tf32<<<dim3((D_SEQ_ + 127) / 128, M_ / 128), 256>>>(X, g1_W, s_g1, t_g1, g1_b, P1, EMB_, D_SEQ_, 0);
    gemm_tf32<<<dim3((EMB_  + 127) / 128, M_ / 128), 256>>>(X, r1_W1, s_r1, t_r1, r1_b1, Y, EMB_, EMB_, 0);
    gemm_tf32<<<dim3((D_SEQ_ + 127) / 128, M_ / 128), 256>>>(Y, r1_W2, nullptr, nullptr, r1_b2, P2, EMB_, D_SEQ_, 1);

    // 8. combine -> gfeat2 (into X, stride EMB2_)
    combine1_kernel<<<dim3(B_, K_), 256>>>(P1, P2, node_feature, kin, a, raw_seq, X);

    // 9-10. BN stats for stage 2
    colstats_partial<<<dim3((EMB2_ + 255) / 256, NCHUNK_), 256>>>(X, psum, psq, EMB2_, M_ / NCHUNK_);
    finalize_stats<<<(EMB2_ + 255) / 256, 256>>>(psum, psq, EMB2_,
        g2_gamma, g2_beta, r2_gamma, r2_beta, s_g2, t_g2, s_r2, t_r2);

    // 11-13. stage-2 GEMMs (reuse P1, P2, Y)
    gemm_tf32<<<dim3((D_SEQ_ + 127) / 128, M_ / 128), 256>>>(X, g2_W, s_g2, t_g2, g2_b, P1, EMB2_, D_SEQ_, 0);
    gemm_tf32<<<dim3((EMB2_ + 127) / 128, M_ / 128), 256>>>(X, r2_W1, s_r2, t_r2, r2_b1, Y, EMB2_, EMB2_, 0);
    gemm_tf32<<<dim3((D_SEQ_ + 127) / 128, M_ / 128), 256>>>(Y, r2_W2, nullptr, nullptr, r2_b2, P2, EMB2_, D_SEQ_, 1);

    // 14. final combine + K-reduce -> graph_feature
    final_kernel<<<B_, 256>>>(P1, P2, X, a2, graph_feature);
}

// round 2
// speedup vs baseline: 1.0010x; 1.0010x over previous
#include <cuda_runtime.h>
#include <cuda_bf16.h>
#include <cstdint>
#include <cstdio>

#define B_      1024
#define K_      11
#define L_KIN_  128
#define L_SUB_  64
#define L_STR_  128
#define D_SEQ_  1280
#define D_STR_  512
#define EMB_    1792        // D_SEQ + D_STR
#define EMB2_   2564        // 2*D_SEQ + 4
#define M_      (B_ * K_)   // 11264
#define NCHUNK_ 44          // 11264 / 44 = 256 rows per chunk

// ---------------- scratch (device globals; no runtime allocation) ----------------
__device__ float g_X [(size_t)M_ * EMB2_];   // gfeat (stride EMB_), later gfeat2 (stride EMB2_)
__device__ float g_Y [(size_t)M_ * EMB2_];   // H (stride EMB_), later H2 (stride EMB2_)
__device__ float g_P1[(size_t)M_ * D_SEQ_];  // F1, later G1
__device__ float g_P2[(size_t)M_ * D_SEQ_];  // F2, later G2
__device__ float g_kin[(size_t)B_ * D_SEQ_];
__device__ float g_psum[NCHUNK_ * EMB2_];
__device__ float g_psq [NCHUNK_ * EMB2_];
__device__ float g_ss  [8 * EMB2_];          // sA,tA,sB,tB per stage

// RES_PROPS table: order G A S P V T C I L N D Q K E M H F R Y W X
__constant__ float c_props[21 * 4] = {
    0,0,0,0,  // G
    1,0,0,0,  // A
    0,0,0,0,  // S
    0,0,0,0,  // P
    1,0,0,0,  // V
    0,0,0,0,  // T
    0,0,0,0,  // C
    1,0,0,0,  // I
    1,0,0,0,  // L
    0,0,0,0,  // N
    0,0,1,0,  // D
    0,0,0,0,  // Q
    0,0,0,1,  // K
    0,0,1,0,  // E
    1,0,0,0,  // M
    0,0,0,1,  // H
    0,1,0,0,  // F
    0,0,0,1,  // R
    0,1,0,0,  // Y
    0,1,0,0,  // W
    0,0,0,0   // X
};

__device__ __forceinline__ float tf32r(float x) {
    unsigned u;
    asm("cvt.rna.tf32.f32 %0, %1;" : "=r"(u) : "f"(x));
    return __uint_as_float(u);
}

__device__ __forceinline__ float sigmoidf_(float x) {
    return 1.f / (1.f + expf(-x));
}

__device__ __forceinline__ void mma_tf32(float* d, const unsigned* a, const unsigned* b) {
    asm volatile(
        "mma.sync.aligned.m16n8k8.row.col.f32.tf32.tf32.f32 "
        "{%0,%1,%2,%3}, {%4,%5,%6,%7}, {%8,%9}, {%0,%1,%2,%3};\n"
        : "+f"(d[0]), "+f"(d[1]), "+f"(d[2]), "+f"(d[3])
        : "r"(a[0]), "r"(a[1]), "r"(a[2]), "r"(a[3]), "r"(b[0]), "r"(b[1]));
}

// ---------------- kernel 1: kin mean over rows 1..127 ----------------
__global__ __launch_bounds__(256) void kin_mean_kernel(const float* __restrict__ kin_in,
                                                       float* __restrict__ kin_out) {
    int b = blockIdx.x;
    const float* base = kin_in + ((size_t)b * L_KIN_ + 1) * D_SEQ_;
    for (int i = threadIdx.x; i < D_SEQ_ / 4; i += blockDim.x) {
        float4 acc = make_float4(0.f, 0.f, 0.f, 0.f);
        for (int r = 0; r < L_KIN_ - 1; ++r) {
            float4 v = *(const float4*)(base + (size_t)r * D_SEQ_ + i * 4);
            acc.x += v.x; acc.y += v.y; acc.z += v.z; acc.w += v.w;
        }
        const float inv = 1.f / 127.f;
        float4 o = make_float4(acc.x * inv, acc.y * inv, acc.z * inv, acc.w * inv);
        *(float4*)(kin_out + (size_t)b * D_SEQ_ + i * 4) = o;
    }
}

// ---------------- kernel 2: build gfeat + node_feature output ----------------
__global__ __launch_bounds__(256) void build_gfeat_kernel(
    const float* __restrict__ sub, const float* __restrict__ n2,
    const float* __restrict__ phos, const int* __restrict__ position,
    float* __restrict__ X, float* __restrict__ node_feature) {
    int b = blockIdx.x, k = blockIdx.y;
    size_t m = (size_t)b * K_ + k;
    const float* src1 = sub + ((size_t)b * L_SUB_ + 1 + k) * D_SEQ_;
    float* dst = X + m * EMB_;
    float* nf  = node_feature + m * D_SEQ_;
    bool mid = (k == K_ / 2);
    for (int i = threadIdx.x; i < D_SEQ_ / 4; i += blockDim.x) {
        float4 v = *(const float4*)(src1 + i * 4);
        *(float4*)(nf + i * 4) = v;
        if (mid) {
            float4 p = *(const float4*)(phos + i * 4);
            v.x += p.x; v.y += p.y; v.z += p.z; v.w += p.w;
        }
        *(float4*)(dst + i * 4) = v;
    }
    int row = position[b] + k - K_ / 2;
    bool ok = (row >= 0 && row < L_STR_);
    const float* src2 = n2 + ((size_t)b * L_STR_ + (ok ? row : 0)) * D_STR_;
    for (int i = threadIdx.x; i < D_STR_ / 4; i += blockDim.x) {
        float4 v = make_float4(0.f, 0.f, 0.f, 0.f);
        if (ok) v = *(const float4*)(src2 + i * 4);
        if (mid) {
            float4 p = *(const float4*)(phos + D_SEQ_ + i * 4);
            v.x += p.x; v.y += p.y; v.z += p.z; v.w += p.w;
        }
        *(float4*)(dst + D_SEQ_ + i * 4) = v;
    }
}

// ---------------- column statistics (two-pass, deterministic) ----------------
__global__ __launch_bounds__(256) void colstats_partial(
    const float* __restrict__ X, float* __restrict__ psum, float* __restrict__ psq,
    int ncols, int rows_per_chunk) {
    int col = blockIdx.x * blockDim.x + threadIdx.x;
    if (col >= ncols) return;
    int r0 = blockIdx.y * rows_per_chunk;
    float s = 0.f, q = 0.f;
    const float* p = X + (size_t)r0 * ncols + col;
    for (int r = 0; r < rows_per_chunk; ++r, p += ncols) {
        float v = *p;
        s += v; q += v * v;
    }
    psum[blockIdx.y * ncols + col] = s;
    psq [blockIdx.y * ncols + col] = q;
}

__global__ __launch_bounds__(256) void finalize_stats(
    const float* __restrict__ psum, const float* __restrict__ psq, int ncols,
    const float* __restrict__ gA, const float* __restrict__ bA,
    const float* __restrict__ gB, const float* __restrict__ bB,
    float* __restrict__ sA, float* __restrict__ tA,
    float* __restrict__ sB, float* __restrict__ tB) {
    int col = blockIdx.x * blockDim.x + threadIdx.x;
    if (col >= ncols) return;
    float s = 0.f, q = 0.f;
    for (int c = 0; c < NCHUNK_; ++c) {
        s += psum[c * ncols + col];
        q += psq [c * ncols + col];
    }
    const float inv_n = 1.f / (float)M_;
    float mean = s * inv_n;
    float var  = q * inv_n - mean * mean;
    float inv  = rsqrtf(var + 1e-5f);
    float sa = gA[col] * inv; sA[col] = sa; tA[col] = bA[col] - mean * sa;
    float sb = gB[col] * inv; sB[col] = sb; tB[col] = bB[col] - mean * sb;
}

// ---------------- tf32 GEMM with fused pre-activation ----------------
// C[M,N] = pre(A)[M,Kd] @ W[Kd,N] + bias
// mode 0: pre(x) = relu(x*s[k]+t[k]);  mode 1: pre(x) = relu(x)
__global__ __launch_bounds__(256) void gemm_tf32(
    const float* __restrict__ A, const float* __restrict__ W,
    const float* __restrict__ s, const float* __restrict__ t,
    const float* __restrict__ bias, float* __restrict__ C,
    int Kd, int N, int mode) {
    __shared__ float As[128][20];   // padded: conflict-free frag loads, 16B-aligned rows
    __shared__ float Bs[16][136];

    const int tid  = threadIdx.x;
    const int bm   = blockIdx.y * 128;
    const int bn   = blockIdx.x * 128;
    const int warp = tid >> 5, lane = tid & 31;
    const int wm = (warp >> 2) << 6;   // 0,64
    const int wn = (warp & 3) << 5;    // 0,32,64,96
    const int g  = lane >> 2, tg = lane & 3;

    float acc[4][4][4];
    #pragma unroll
    for (int mt = 0; mt < 4; ++mt)
        #pragma unroll
        for (int nt = 0; nt < 4; ++nt)
            #pragma unroll
            for (int i = 0; i < 4; ++i) acc[mt][nt][i] = 0.f;

    const int ktiles = (Kd + 15) >> 4;
    for (int kt = 0; kt < ktiles; ++kt) {
        const int k0 = kt << 4;
        // A tile: 128 x 16
        #pragma unroll
        for (int j = 0; j < 2; ++j) {
            int f   = tid + (j << 8);
            int row = f >> 2;
            int c4  = (f & 3) << 2;
            int gk  = k0 + c4;
            float4 v = make_float4(0.f, 0.f, 0.f, 0.f);
            if (gk < Kd) {   // Kd % 4 == 0 so float4 granularity is exact
                v = *(const float4*)(A + (size_t)(bm + row) * Kd + gk);
                if (mode == 0) {
                    v.x = fmaxf(fmaf(v.x, s[gk],     t[gk]),     0.f);
                    v.y = fmaxf(fmaf(v.y, s[gk + 1], t[gk + 1]), 0.f);
                    v.z = fmaxf(fmaf(v.z, s[gk + 2], t[gk + 2]), 0.f);
                    v.w = fmaxf(fmaf(v.w, s[gk + 3], t[gk + 3]), 0.f);
                } else {
                    v.x = fmaxf(v.x, 0.f); v.y = fmaxf(v.y, 0.f);
                    v.z = fmaxf(v.z, 0.f); v.w = fmaxf(v.w, 0.f);
                }
                v.x = tf32r(v.x); v.y = tf32r(v.y); v.z = tf32r(v.z); v.w = tf32r(v.w);
            }
            *(float4*)&As[row][c4] = v;
        }
        // B tile: 16 x 128
        #pragma unroll
        for (int j = 0; j < 2; ++j) {
            int f   = tid + (j << 8);
            int row = f >> 5;
            int c4  = (f & 31) << 2;
            int gk  = k0 + row;
            int gn  = bn + c4;
            float4 v = make_float4(0.f, 0.f, 0.f, 0.f);
            if (gk < Kd && gn < N) {   // N % 4 == 0
                v = *(const float4*)(W + (size_t)gk * N + gn);
                v.x = tf32r(v.x); v.y = tf32r(v.y); v.z = tf32r(v.z); v.w = tf32r(v.w);
            }
            *(float4*)&Bs[row][c4] = v;
        }
        __syncthreads();

        #pragma unroll
        for (int kk = 0; kk < 2; ++kk) {
            const int kb = kk << 3;
            unsigned af[4][4], bf[4][2];
            #pragma unroll
            for (int mt = 0; mt < 4; ++mt) {
                int r = wm + (mt << 4);
                af[mt][0] = __float_as_uint(As[r + g][kb + tg]);
                af[mt][1] = __float_as_uint(As[r + g + 8][kb + tg]);
                af[mt][2] = __float_as_uint(As[r + g][kb + tg + 4]);
                af[mt][3] = __float_as_uint(As[r + g + 8][kb + tg + 4]);
            }
            #pragma unroll
            for (int nt = 0; nt < 4; ++nt) {
                int c = wn + (nt << 3) + g;
                bf[nt][0] = __float_as_uint(Bs[kb + tg][c]);
                bf[nt][1] = __float_as_uint(Bs[kb + tg + 4][c]);
            }
            #pragma unroll
            for (int mt = 0; mt < 4; ++mt)
                #pragma unroll
                for (int nt = 0; nt < 4; ++nt)
                    mma_tf32(acc[mt][nt], af[mt], bf[nt]);
        }
        __syncthreads();
    }

    // epilogue: += bias, store
    #pragma unroll
    for (int mt = 0; mt < 4; ++mt) {
        int r = bm + wm + (mt << 4);
        #pragma unroll
        for (int nt = 0; nt < 4; ++nt) {
            int c = bn + wn + (nt << 3) + (tg << 1);
            if (c < N) {   // N even, so c+1 < N too
                float b0 = bias[c], b1 = bias[c + 1];
                C[(size_t)(r + g) * N + c]         = acc[mt][nt][0] + b0;
                C[(size_t)(r + g) * N + c + 1]     = acc[mt][nt][1] + b1;
                C[(size_t)(r + g + 8) * N + c]     = acc[mt][nt][2] + b0;
                C[(size_t)(r + g + 8) * N + c + 1] = acc[mt][nt][3] + b1;
            }
        }
    }
}

// ---------------- combine stage 1 -> build gfeat2 ----------------
__global__ __launch_bounds__(256) void combine1_kernel(
    const float* __restrict__ F1, const float* __restrict__ F2,
    const float* __restrict__ nf, const float* __restrict__ kin,
    const float* __restrict__ a, const int* __restrict__ raw_seq,
    float* __restrict__ X2) {
    int b = blockIdx.x, k = blockIdx.y;
    size_t m = (size_t)b * K_ + k;
    float a0 = a[0], a1 = a[1];
    const float* f1 = F1 + m * D_SEQ_;
    const float* f2 = F2 + m * D_SEQ_;
    const float* g1 = nf + m * D_SEQ_;
    const float* kb = kin + (size_t)b * D_SEQ_;
    float* dst = X2 + m * EMB2_;
    for (int i = threadIdx.x; i < D_SEQ_ / 4; i += blockDim.x) {
        float4 v1 = *(const float4*)(f1 + i * 4);
        float4 v2 = *(const float4*)(f2 + i * 4);
        float4 vg = *(const float4*)(g1 + i * 4);
        float4 r;
        r.x = sigmoidf_(v1.x) * vg.x * a0 + v2.x * a1;
        r.y = sigmoidf_(v1.y) * vg.y * a0 + v2.y * a1;
        r.z = sigmoidf_(v1.z) * vg.z * a0 + v2.z * a1;
        r.w = sigmoidf_(v1.w) * vg.w * a0 + v2.w * a1;
        *(float4*)(dst + i * 4) = r;
        *(float4*)(dst + D_SEQ_ + i * 4) = *(const float4*)(kb + i * 4);
    }
    if (threadIdx.x < 4) {
        int sid = raw_seq[m];
        dst[2 * D_SEQ_ + threadIdx.x] = c_props[sid * 4 + threadIdx.x];
    }
}

// ---------------- final combine + reduce over K ----------------
__global__ __launch_bounds__(256) void final_kernel(
    const float* __restrict__ G1, const float* __restrict__ G2,
    const float* __restrict__ X2, const float* __restrict__ a2,
    float* __restrict__ out) {
    int b = blockIdx.x;
    float s0 = a2[0], s1 = a2[1];
    for (int i = threadIdx.x; i < D_SEQ_ / 4; i += blockDim.x) {
        float4 acc = make_float4(0.f, 0.f, 0.f, 0.f);
        for (int k = 0; k < K_; ++k) {
            size_t m = (size_t)b * K_ + k;
            float4 f1 = *(const float4*)(G1 + m * D_SEQ_ + i * 4);
            float4 f2 = *(const float4*)(G2 + m * D_SEQ_ + i * 4);
            float4 gn = *(const float4*)(X2 + m * EMB2_ + i * 4);
            acc.x += sigmoidf_(f1.x) * gn.x * s0 + f2.x * s1;
            acc.y += sigmoidf_(f1.y) * gn.y * s0 + f2.y * s1;
            acc.z += sigmoidf_(f1.z) * gn.z * s0 + f2.z * s1;
            acc.w += sigmoidf_(f1.w) * gn.w * s0 + f2.w * s1;
        }
        *(float4*)(out + (size_t)b * D_SEQ_ + i * 4) = acc;
    }
}

// ---------------- launch ----------------
extern "C" void kernel_launch(void* const* d_in, const int* in_sizes, int n_in,
                              void* d_out, int out_size) {
    const float* kin_in   = (const float*)d_in[0];
    const float* sub      = (const float*)d_in[1];
    const float* n2       = (const float*)d_in[2];
    // d_in[3] = plddt (unused by reference)
    const float* a        = (const float*)d_in[4];
    const float* a2       = (const float*)d_in[5];
    const float* phos     = (const float*)d_in[6];
    const float* g1_gamma = (const float*)d_in[7];
    const float* g1_beta  = (const float*)d_in[8];
    const float* g1_W     = (const float*)d_in[9];
    const float* g1_b     = (const float*)d_in[10];
    const float* r1_gamma = (const float*)d_in[11];
    const float* r1_beta  = (const float*)d_in[12];
    const float* r1_W1    = (const float*)d_in[13];
    const float* r1_b1    = (const float*)d_in[14];
    const float* r1_W2    = (const float*)d_in[15];
    const float* r1_b2    = (const float*)d_in[16];
    const float* g2_gamma = (const float*)d_in[17];
    const float* g2_beta  = (const float*)d_in[18];
    const float* g2_W     = (const float*)d_in[19];
    const float* g2_b     = (const float*)d_in[20];
    const float* r2_gamma = (const float*)d_in[21];
    const float* r2_beta  = (const float*)d_in[22];
    const float* r2_W1    = (const float*)d_in[23];
    const float* r2_b1    = (const float*)d_in[24];
    const float* r2_W2    = (const float*)d_in[25];
    const float* r2_b2    = (const float*)d_in[26];
    const int*   position = (const int*)d_in[27];
    const int*   raw_seq  = (const int*)d_in[28];

    float* out = (float*)d_out;
    float* graph_feature = out;                             // (B, D_SEQ)
    float* node_feature  = out + (size_t)B_ * D_SEQ_;       // (B, K, D_SEQ)

    float *X, *Y, *P1, *P2, *kin, *psum, *psq, *ss;
    cudaGetSymbolAddress((void**)&X,    g_X);
    cudaGetSymbolAddress((void**)&Y,    g_Y);
    cudaGetSymbolAddress((void**)&P1,   g_P1);
    cudaGetSymbolAddress((void**)&P2,   g_P2);
    cudaGetSymbolAddress((void**)&kin,  g_kin);
    cudaGetSymbolAddress((void**)&psum, g_psum);
    cudaGetSymbolAddress((void**)&psq,  g_psq);
    cudaGetSymbolAddress((void**)&ss,   g_ss);

    float* s_g1 = ss + 0 * EMB2_;
    float* t_g1 = ss + 1 * EMB2_;
    float* s_r1 = ss + 2 * EMB2_;
    float* t_r1 = ss + 3 * EMB2_;
    float* s_g2 = ss + 4 * EMB2_;
    float* t_g2 = ss + 5 * EMB2_;
    float* s_r2 = ss + 6 * EMB2_;
    float* t_r2 = ss + 7 * EMB2_;

    // 1. kin mean
    kin_mean_kernel<<<B_, 256>>>(kin_in, kin);

    // 2. build gfeat (into X, stride EMB_) + node_feature output
    build_gfeat_kernel<<<dim3(B_, K_), 256>>>(sub, n2, phos, position, X, node_feature);

    // 3-4. BN stats for stage 1
    colstats_partial<<<dim3((EMB_ + 255) / 256, NCHUNK_), 256>>>(X, psum, psq, EMB_, M_ / NCHUNK_);
    finalize_stats<<<(EMB_ + 255) / 256, 256>>>(psum, psq, EMB_,
        g1_gamma, g1_beta, r1_gamma, r1_beta, s_g1, t_g1, s_r1, t_r1);

    // 5-7. stage-1 GEMMs
    gemm_tf32<<<dim3((D_SEQ_ + 127) / 128, M_ / 128), 256>>>(X, g1_W, s_g1, t_g1, g1_b, P1, EMB_, D_SEQ_, 0);
    gemm_tf32<<<dim3((EMB_  + 127) / 128, M_ / 128), 256>>>(X, r1_W1, s_r1, t_r1, r1_b1, Y, EMB_, EMB_, 0);
    gemm_tf32<<<dim3((D_SEQ_ + 127) / 128, M_ / 128), 256>>>(Y, r1_W2, nullptr, nullptr, r1_b2, P2, EMB_, D_SEQ_, 1);

    // 8. combine -> gfeat2 (into X, stride EMB2_)
    combine1_kernel<<<dim3(B_, K_), 256>>>(P1, P2, node_feature, kin, a, raw_seq, X);

    // 9-10. BN stats for stage 2
    colstats_partial<<<dim3((EMB2_ + 255) / 256, NCHUNK_), 256>>>(X, psum, psq, EMB2_, M_ / NCHUNK_);
    finalize_stats<<<(EMB2_ + 255) / 256, 256>>>(psum, psq, EMB2_,
        g2_gamma, g2_beta, r2_gamma, r2_beta, s_g2, t_g2, s_r2, t_r2);

    // 11-13. stage-2 GEMMs (reuse P1, P2, Y)
    gemm_tf32<<<dim3((D_SEQ_ + 127) / 128, M_ / 128), 256>>>(X, g2_W, s_g2, t_g2, g2_b, P1, EMB2_, D_SEQ_, 0);
    gemm_tf32<<<dim3((EMB2_ + 127) / 128, M_ / 128), 256>>>(X, r2_W1, s_r2, t_r2, r2_b1, Y, EMB2_, EMB2_, 0);
    gemm_tf32<<<dim3((D_SEQ_ + 127) / 128, M_ / 128), 256>>>(Y, r2_W2, nullptr, nullptr, r2_b2, P2, EMB2_, D_SEQ_, 1);

    // 14. final combine + K-reduce -> graph_feature
    final_kernel<<<B_, 256>>>(P1, P2, X, a2, graph_feature);
}

// round 3
// speedup vs baseline: 1.2384x; 1.2372x over previous
#include <cuda_runtime.h>
#include <cuda_bf16.h>
#include <cstdint>
#include <cstdio>

#define B_      1024
#define K_      11
#define L_KIN_  128
#define L_SUB_  64
#define L_STR_  128
#define D_SEQ_  1280
#define D_STR_  512
#define EMB_    1792        // D_SEQ + D_STR
#define EMB2_   2564        // 2*D_SEQ + 4
#define M_      (B_ * K_)   // 11264
#define NCHUNK_ 44          // 11264 / 44 = 256 rows per chunk

#define BM_ 128
#define BN_ 128
#define BK_ 32
// smem float counts
#define AS_STRIDE 36
#define BS_STRIDE 132
#define AS_BUF (BM_ * AS_STRIDE)        // 4608
#define BS_BUF (BK_ * BS_STRIDE)        // 4224
#define SMEM_FLOATS (2 * AS_BUF + 2 * BS_BUF)   // 17664 -> 70656 bytes

// ---------------- scratch (device globals; no runtime allocation) ----------------
__device__ float g_X [(size_t)M_ * EMB2_];   // gfeat (stride EMB_), later gfeat2 (stride EMB2_)
__device__ float g_Y [(size_t)M_ * EMB2_];   // H (stride EMB_), later H2 (stride EMB2_)
__device__ float g_P1[(size_t)M_ * D_SEQ_];  // F1, later G1
__device__ float g_P2[(size_t)M_ * D_SEQ_];  // F2, later G2
__device__ float g_kin[(size_t)B_ * D_SEQ_];
__device__ float g_psum[NCHUNK_ * EMB2_];
__device__ float g_psq [NCHUNK_ * EMB2_];
__device__ float g_ss  [8 * EMB2_];          // sA,tA,sB,tB per stage

// RES_PROPS table: order G A S P V T C I L N D Q K E M H F R Y W X
__constant__ float c_props[21 * 4] = {
    0,0,0,0,  1,0,0,0,  0,0,0,0,  0,0,0,0,  1,0,0,0,  0,0,0,0,  0,0,0,0,
    1,0,0,0,  1,0,0,0,  0,0,0,0,  0,0,1,0,  0,0,0,0,  0,0,0,1,  0,0,1,0,
    1,0,0,0,  0,0,0,1,  0,1,0,0,  0,0,0,1,  0,1,0,0,  0,1,0,0,  0,0,0,0
};

__device__ __forceinline__ float tf32r(float x) {
    unsigned u;
    asm("cvt.rna.tf32.f32 %0, %1;" : "=r"(u) : "f"(x));
    return __uint_as_float(u);
}

__device__ __forceinline__ float sigmoidf_(float x) {
    return 1.f / (1.f + expf(-x));
}

__device__ __forceinline__ void mma_tf32(float* d, const unsigned* a, const unsigned* b) {
    asm volatile(
        "mma.sync.aligned.m16n8k8.row.col.f32.tf32.tf32.f32 "
        "{%0,%1,%2,%3}, {%4,%5,%6,%7}, {%8,%9}, {%0,%1,%2,%3};\n"
        : "+f"(d[0]), "+f"(d[1]), "+f"(d[2]), "+f"(d[3])
        : "r"(a[0]), "r"(a[1]), "r"(a[2]), "r"(a[3]), "r"(b[0]), "r"(b[1]));
}

// ---------------- kernel 1: kin mean over rows 1..127 ----------------
__global__ __launch_bounds__(256) void kin_mean_kernel(const float* __restrict__ kin_in,
                                                       float* __restrict__ kin_out) {
    int b = blockIdx.x;
    const float* base = kin_in + ((size_t)b * L_KIN_ + 1) * D_SEQ_;
    for (int i = threadIdx.x; i < D_SEQ_ / 4; i += blockDim.x) {
        float4 acc = make_float4(0.f, 0.f, 0.f, 0.f);
        #pragma unroll 4
        for (int r = 0; r < L_KIN_ - 1; ++r) {
            float4 v = *(const float4*)(base + (size_t)r * D_SEQ_ + i * 4);
            acc.x += v.x; acc.y += v.y; acc.z += v.z; acc.w += v.w;
        }
        const float inv = 1.f / 127.f;
        float4 o = make_float4(acc.x * inv, acc.y * inv, acc.z * inv, acc.w * inv);
        *(float4*)(kin_out + (size_t)b * D_SEQ_ + i * 4) = o;
    }
}

// ---------------- kernel 2: build gfeat + node_feature output ----------------
__global__ __launch_bounds__(256) void build_gfeat_kernel(
    const float* __restrict__ sub, const float* __restrict__ n2,
    const float* __restrict__ phos, const int* __restrict__ position,
    float* __restrict__ X, float* __restrict__ node_feature) {
    int b = blockIdx.x, k = blockIdx.y;
    size_t m = (size_t)b * K_ + k;
    const float* src1 = sub + ((size_t)b * L_SUB_ + 1 + k) * D_SEQ_;
    float* dst = X + m * EMB_;
    float* nf  = node_feature + m * D_SEQ_;
    bool mid = (k == K_ / 2);
    for (int i = threadIdx.x; i < D_SEQ_ / 4; i += blockDim.x) {
        float4 v = *(const float4*)(src1 + i * 4);
        *(float4*)(nf + i * 4) = v;
        if (mid) {
            float4 p = *(const float4*)(phos + i * 4);
            v.x += p.x; v.y += p.y; v.z += p.z; v.w += p.w;
        }
        *(float4*)(dst + i * 4) = v;
    }
    int row = position[b] + k - K_ / 2;
    bool ok = (row >= 0 && row < L_STR_);
    const float* src2 = n2 + ((size_t)b * L_STR_ + (ok ? row : 0)) * D_STR_;
    for (int i = threadIdx.x; i < D_STR_ / 4; i += blockDim.x) {
        float4 v = make_float4(0.f, 0.f, 0.f, 0.f);
        if (ok) v = *(const float4*)(src2 + i * 4);
        if (mid) {
            float4 p = *(const float4*)(phos + D_SEQ_ + i * 4);
            v.x += p.x; v.y += p.y; v.z += p.z; v.w += p.w;
        }
        *(float4*)(dst + D_SEQ_ + i * 4) = v;
    }
}

// ---------------- column statistics (two-pass, deterministic) ----------------
__global__ __launch_bounds__(256) void colstats_partial(
    const float* __restrict__ X, float* __restrict__ psum, float* __restrict__ psq,
    int ncols, int rows_per_chunk) {
    int col = blockIdx.x * blockDim.x + threadIdx.x;
    if (col >= ncols) return;
    int r0 = blockIdx.y * rows_per_chunk;
    float s = 0.f, q = 0.f;
    const float* p = X + (size_t)r0 * ncols + col;
    #pragma unroll 4
    for (int r = 0; r < rows_per_chunk; ++r, p += ncols) {
        float v = *p;
        s += v; q += v * v;
    }
    psum[blockIdx.y * ncols + col] = s;
    psq [blockIdx.y * ncols + col] = q;
}

__global__ __launch_bounds__(256) void finalize_stats(
    const float* __restrict__ psum, const float* __restrict__ psq, int ncols,
    const float* __restrict__ gA, const float* __restrict__ bA,
    const float* __restrict__ gB, const float* __restrict__ bB,
    float* __restrict__ sA, float* __restrict__ tA,
    float* __restrict__ sB, float* __restrict__ tB) {
    int col = blockIdx.x * blockDim.x + threadIdx.x;
    if (col >= ncols) return;
    float s = 0.f, q = 0.f;
    for (int c = 0; c < NCHUNK_; ++c) {
        s += psum[c * ncols + col];
        q += psq [c * ncols + col];
    }
    const float inv_n = 1.f / (float)M_;
    float mean = s * inv_n;
    float var  = q * inv_n - mean * mean;
    float inv  = rsqrtf(var + 1e-5f);
    float sa = gA[col] * inv; sA[col] = sa; tA[col] = bA[col] - mean * sa;
    float sb = gB[col] * inv; sB[col] = sb; tB[col] = bB[col] - mean * sb;
}

// ---------------- tf32 GEMM, double-buffered pipeline ----------------
// C[M,N] = pre(A)[M,Kd] @ W[Kd,N] + bias
// mode 0: pre(x) = relu(x*s[k]+t[k]);  mode 1: pre(x) = relu(x)
__global__ __launch_bounds__(256) void gemm_tf32_pipe(
    const float* __restrict__ A, const float* __restrict__ W,
    const float* __restrict__ s, const float* __restrict__ t,
    const float* __restrict__ bias, float* __restrict__ C,
    int Kd, int N, int mode) {
    extern __shared__ float smem[];
    float* sA = smem;                 // [2][BM_][AS_STRIDE]
    float* sB = smem + 2 * AS_BUF;    // [2][BK_][BS_STRIDE]

    const int tid  = threadIdx.x;
    const int bm   = blockIdx.y * BM_;
    const int bn   = blockIdx.x * BN_;
    const int warp = tid >> 5, lane = tid & 31;
    const int wm = (warp >> 2) << 6;   // 0,64
    const int wn = (warp & 3) << 5;    // 0,32,64,96
    const int g  = lane >> 2, tg = lane & 3;

    // per-thread global-load coordinates (fixed across tiles)
    const int a_row[4] = { (tid + 0*256) >> 3, (tid + 1*256) >> 3, (tid + 2*256) >> 3, (tid + 3*256) >> 3 };
    const int a_c4     = (tid & 7) << 2;
    const int b_row[4] = { (tid + 0*256) >> 5, (tid + 1*256) >> 5, (tid + 2*256) >> 5, (tid + 3*256) >> 5 };
    const int b_c4     = (tid & 31) << 2;
    const int gn       = bn + b_c4;
    const bool n_ok    = (gn < N);

    float4 aregs[4], bregs[4];

    float acc[4][4][4];
    #pragma unroll
    for (int mt = 0; mt < 4; ++mt)
        #pragma unroll
        for (int nt = 0; nt < 4; ++nt)
            #pragma unroll
            for (int i = 0; i < 4; ++i) acc[mt][nt][i] = 0.f;

    const int ktiles = (Kd + BK_ - 1) / BK_;

    // ---- load tile kt into regs ----
    auto load_tile = [&](int kt) {
        const int k0 = kt * BK_;
        const int gka = k0 + a_c4;
        #pragma unroll
        for (int j = 0; j < 4; ++j) {
            float4 v = make_float4(0.f, 0.f, 0.f, 0.f);
            if (gka < Kd)
                v = *(const float4*)(A + (size_t)(bm + a_row[j]) * Kd + gka);
            aregs[j] = v;
        }
        #pragma unroll
        for (int j = 0; j < 4; ++j) {
            int gk = k0 + b_row[j];
            float4 v = make_float4(0.f, 0.f, 0.f, 0.f);
            if (gk < Kd && n_ok)
                v = *(const float4*)(W + (size_t)gk * N + gn);
            bregs[j] = v;
        }
    };

    // ---- transform + store regs into smem buffer ----
    auto store_tile = [&](int buf, int kt) {
        const int k0 = kt * BK_;
        const int gka = k0 + a_c4;
        if (gka < Kd) {
            float4 sc = make_float4(1.f, 1.f, 1.f, 1.f), sh = make_float4(0.f, 0.f, 0.f, 0.f);
            if (mode == 0) {
                sc = *(const float4*)(s + gka);
                sh = *(const float4*)(t + gka);
            }
            #pragma unroll
            for (int j = 0; j < 4; ++j) {
                float4 v = aregs[j];
                v.x = tf32r(fmaxf(fmaf(v.x, sc.x, sh.x), 0.f));
                v.y = tf32r(fmaxf(fmaf(v.y, sc.y, sh.y), 0.f));
                v.z = tf32r(fmaxf(fmaf(v.z, sc.z, sh.z), 0.f));
                v.w = tf32r(fmaxf(fmaf(v.w, sc.w, sh.w), 0.f));
                *(float4*)&sA[buf * AS_BUF + a_row[j] * AS_STRIDE + a_c4] = v;
            }
        } else {
            #pragma unroll
            for (int j = 0; j < 4; ++j)
                *(float4*)&sA[buf * AS_BUF + a_row[j] * AS_STRIDE + a_c4] =
                    make_float4(0.f, 0.f, 0.f, 0.f);
        }
        #pragma unroll
        for (int j = 0; j < 4; ++j) {
            float4 v = bregs[j];
            v.x = tf32r(v.x); v.y = tf32r(v.y); v.z = tf32r(v.z); v.w = tf32r(v.w);
            *(float4*)&sB[buf * BS_BUF + b_row[j] * BS_STRIDE + b_c4] = v;
        }
    };

    // ---- compute one BK_ slab from smem buffer ----
    auto compute = [&](int buf) {
        const float* pA = sA + buf * AS_BUF;
        const float* pB = sB + buf * BS_BUF;
        #pragma unroll
        for (int kk = 0; kk < 4; ++kk) {
            const int kb = kk << 3;
            unsigned af[4][4], bf[4][2];
            #pragma unroll
            for (int mt = 0; mt < 4; ++mt) {
                int r = wm + (mt << 4);
                af[mt][0] = __float_as_uint(pA[(r + g) * AS_STRIDE + kb + tg]);
                af[mt][1] = __float_as_uint(pA[(r + g + 8) * AS_STRIDE + kb + tg]);
                af[mt][2] = __float_as_uint(pA[(r + g) * AS_STRIDE + kb + tg + 4]);
                af[mt][3] = __float_as_uint(pA[(r + g + 8) * AS_STRIDE + kb + tg + 4]);
            }
            #pragma unroll
            for (int nt = 0; nt < 4; ++nt) {
                int c = wn + (nt << 3) + g;
                bf[nt][0] = __float_as_uint(pB[(kb + tg) * BS_STRIDE + c]);
                bf[nt][1] = __float_as_uint(pB[(kb + tg + 4) * BS_STRIDE + c]);
            }
            #pragma unroll
            for (int mt = 0; mt < 4; ++mt)
                #pragma unroll
                for (int nt = 0; nt < 4; ++nt)
                    mma_tf32(acc[mt][nt], af[mt], bf[nt]);
        }
    };

    // ---- pipeline ----
    load_tile(0);
    store_tile(0, 0);
    __syncthreads();
    int buf = 0;
    for (int kt = 0; kt < ktiles; ++kt) {
        if (kt + 1 < ktiles) load_tile(kt + 1);   // issue next global loads early
        compute(buf);
        if (kt + 1 < ktiles) {
            store_tile(buf ^ 1, kt + 1);
            __syncthreads();
        }
        buf ^= 1;
    }

    // epilogue: += bias, store
    #pragma unroll
    for (int mt = 0; mt < 4; ++mt) {
        int r = bm + wm + (mt << 4);
        #pragma unroll
        for (int nt = 0; nt < 4; ++nt) {
            int c = bn + wn + (nt << 3) + (tg << 1);
            if (c < N) {   // N even, so c+1 < N too
                float b0 = bias[c], b1 = bias[c + 1];
                C[(size_t)(r + g) * N + c]         = acc[mt][nt][0] + b0;
                C[(size_t)(r + g) * N + c + 1]     = acc[mt][nt][1] + b1;
                C[(size_t)(r + g + 8) * N + c]     = acc[mt][nt][2] + b0;
                C[(size_t)(r + g + 8) * N + c + 1] = acc[mt][nt][3] + b1;
            }
        }
    }
}

// ---------------- combine stage 1 -> build gfeat2 ----------------
__global__ __launch_bounds__(256) void combine1_kernel(
    const float* __restrict__ F1, const float* __restrict__ F2,
    const float* __restrict__ nf, const float* __restrict__ kin,
    const float* __restrict__ a, const int* __restrict__ raw_seq,
    float* __restrict__ X2) {
    int b = blockIdx.x, k = blockIdx.y;
    size_t m = (size_t)b * K_ + k;
    float a0 = a[0], a1 = a[1];
    const float* f1 = F1 + m * D_SEQ_;
    const float* f2 = F2 + m * D_SEQ_;
    const float* g1 = nf + m * D_SEQ_;
    const float* kb = kin + (size_t)b * D_SEQ_;
    float* dst = X2 + m * EMB2_;
    for (int i = threadIdx.x; i < D_SEQ_ / 4; i += blockDim.x) {
        float4 v1 = *(const float4*)(f1 + i * 4);
        float4 v2 = *(const float4*)(f2 + i * 4);
        float4 vg = *(const float4*)(g1 + i * 4);
        float4 r;
        r.x = sigmoidf_(v1.x) * vg.x * a0 + v2.x * a1;
        r.y = sigmoidf_(v1.y) * vg.y * a0 + v2.y * a1;
        r.z = sigmoidf_(v1.z) * vg.z * a0 + v2.z * a1;
        r.w = sigmoidf_(v1.w) * vg.w * a0 + v2.w * a1;
        *(float4*)(dst + i * 4) = r;
        *(float4*)(dst + D_SEQ_ + i * 4) = *(const float4*)(kb + i * 4);
    }
    if (threadIdx.x < 4) {
        int sid = raw_seq[m];
        dst[2 * D_SEQ_ + threadIdx.x] = c_props[sid * 4 + threadIdx.x];
    }
}

// ---------------- final combine + reduce over K ----------------
__global__ __launch_bounds__(256) void final_kernel(
    const float* __restrict__ G1, const float* __restrict__ G2,
    const float* __restrict__ X2, const float* __restrict__ a2,
    float* __restrict__ out) {
    int b = blockIdx.x;
    float s0 = a2[0], s1 = a2[1];
    for (int i = threadIdx.x; i < D_SEQ_ / 4; i += blockDim.x) {
        float4 acc = make_float4(0.f, 0.f, 0.f, 0.f);
        for (int k = 0; k < K_; ++k) {
            size_t m = (size_t)b * K_ + k;
            float4 f1 = *(const float4*)(G1 + m * D_SEQ_ + i * 4);
            float4 f2 = *(const float4*)(G2 + m * D_SEQ_ + i * 4);
            float4 gn = *(const float4*)(X2 + m * EMB2_ + i * 4);
            acc.x += sigmoidf_(f1.x) * gn.x * s0 + f2.x * s1;
            acc.y += sigmoidf_(f1.y) * gn.y * s0 + f2.y * s1;
            acc.z += sigmoidf_(f1.z) * gn.z * s0 + f2.z * s1;
            acc.w += sigmoidf_(f1.w) * gn.w * s0 + f2.w * s1;
        }
        *(float4*)(out + (size_t)b * D_SEQ_ + i * 4) = acc;
    }
}

// ---------------- launch ----------------
extern "C" void kernel_launch(void* const* d_in, const int* in_sizes, int n_in,
                              void* d_out, int out_size) {
    const float* kin_in   = (const float*)d_in[0];
    const float* sub      = (const float*)d_in[1];
    const float* n2       = (const float*)d_in[2];
    // d_in[3] = plddt (unused by reference)
    const float* a        = (const float*)d_in[4];
    const float* a2       = (const float*)d_in[5];
    const float* phos     = (const float*)d_in[6];
    const float* g1_gamma = (const float*)d_in[7];
    const float* g1_beta  = (const float*)d_in[8];
    const float* g1_W     = (const float*)d_in[9];
    const float* g1_b     = (const float*)d_in[10];
    const float* r1_gamma = (const float*)d_in[11];
    const float* r1_beta  = (const float*)d_in[12];
    const float* r1_W1    = (const float*)d_in[13];
    const float* r1_b1    = (const float*)d_in[14];
    const float* r1_W2    = (const float*)d_in[15];
    const float* r1_b2    = (const float*)d_in[16];
    const float* g2_gamma = (const float*)d_in[17];
    const float* g2_beta  = (const float*)d_in[18];
    const float* g2_W     = (const float*)d_in[19];
    const float* g2_b     = (const float*)d_in[20];
    const float* r2_gamma = (const float*)d_in[21];
    const float* r2_beta  = (const float*)d_in[22];
    const float* r2_W1    = (const float*)d_in[23];
    const float* r2_b1    = (const float*)d_in[24];
    const float* r2_W2    = (const float*)d_in[25];
    const float* r2_b2    = (const float*)d_in[26];
    const int*   position = (const int*)d_in[27];
    const int*   raw_seq  = (const int*)d_in[28];

    float* out = (float*)d_out;
    float* graph_feature = out;                             // (B, D_SEQ)
    float* node_feature  = out + (size_t)B_ * D_SEQ_;       // (B, K, D_SEQ)

    float *X, *Y, *P1, *P2, *kin, *psum, *psq, *ss;
    cudaGetSymbolAddress((void**)&X,    g_X);
    cudaGetSymbolAddress((void**)&Y,    g_Y);
    cudaGetSymbolAddress((void**)&P1,   g_P1);
    cudaGetSymbolAddress((void**)&P2,   g_P2);
    cudaGetSymbolAddress((void**)&kin,  g_kin);
    cudaGetSymbolAddress((void**)&psum, g_psum);
    cudaGetSymbolAddress((void**)&psq,  g_psq);
    cudaGetSymbolAddress((void**)&ss,   g_ss);

    const int smem_bytes = SMEM_FLOATS * (int)sizeof(float);   // 70656
    cudaFuncSetAttribute(gemm_tf32_pipe,
                         cudaFuncAttributeMaxDynamicSharedMemorySize, smem_bytes);

    float* s_g1 = ss + 0 * EMB2_;
    float* t_g1 = ss + 1 * EMB2_;
    float* s_r1 = ss + 2 * EMB2_;
    float* t_r1 = ss + 3 * EMB2_;
    float* s_g2 = ss + 4 * EMB2_;
    float* t_g2 = ss + 5 * EMB2_;
    float* s_r2 = ss + 6 * EMB2_;
    float* t_r2 = ss + 7 * EMB2_;

    // 1. kin mean
    kin_mean_kernel<<<B_, 256>>>(kin_in, kin);

    // 2. build gfeat (into X, stride EMB_) + node_feature output
    build_gfeat_kernel<<<dim3(B_, K_), 256>>>(sub, n2, phos, position, X, node_feature);

    // 3-4. BN stats for stage 1
    colstats_partial<<<dim3((EMB_ + 255) / 256, NCHUNK_), 256>>>(X, psum, psq, EMB_, M_ / NCHUNK_);
    finalize_stats<<<(EMB_ + 255) / 256, 256>>>(psum, psq, EMB_,
        g1_gamma, g1_beta, r1_gamma, r1_beta, s_g1, t_g1, s_r1, t_r1);

    // 5-7. stage-1 GEMMs
    gemm_tf32_pipe<<<dim3(D_SEQ_ / BN_, M_ / BM_), 256, smem_bytes>>>(X, g1_W, s_g1, t_g1, g1_b, P1, EMB_, D_SEQ_, 0);
    gemm_tf32_pipe<<<dim3(EMB_ / BN_, M_ / BM_), 256, smem_bytes>>>(X, r1_W1, s_r1, t_r1, r1_b1, Y, EMB_, EMB_, 0);
    gemm_tf32_pipe<<<dim3(D_SEQ_ / BN_, M_ / BM_), 256, smem_bytes>>>(Y, r1_W2, nullptr, nullptr, r1_b2, P2, EMB_, D_SEQ_, 1);

    // 8. combine -> gfeat2 (into X, stride EMB2_)
    combine1_kernel<<<dim3(B_, K_), 256>>>(P1, P2, node_feature, kin, a, raw_seq, X);

    // 9-10. BN stats for stage 2
    colstats_partial<<<dim3((EMB2_ + 255) / 256, NCHUNK_), 256>>>(X, psum, psq, EMB2_, M_ / NCHUNK_);
    finalize_stats<<<(EMB2_ + 255) / 256, 256>>>(psum, psq, EMB2_,
        g2_gamma, g2_beta, r2_gamma, r2_beta, s_g2, t_g2, s_r2, t_r2);

    // 11-13. stage-2 GEMMs (reuse P1, P2, Y)
    gemm_tf32_pipe<<<dim3(D_SEQ_ / BN_, M_ / BM_), 256, smem_bytes>>>(X, g2_W, s_g2, t_g2, g2_b, P1, EMB2_, D_SEQ_, 0);
    gemm_tf32_pipe<<<dim3((EMB2_ + BN_ - 1) / BN_, M_ / BM_), 256, smem_bytes>>>(X, r2_W1, s_r2, t_r2, r2_b1, Y, EMB2_, EMB2_, 0);
    gemm_tf32_pipe<<<dim3(D_SEQ_ / BN_, M_ / BM_), 256, smem_bytes>>>(Y, r2_W2, nullptr, nullptr, r2_b2, P2, EMB2_, D_SEQ_, 1);

    // 14. final combine + K-reduce -> graph_feature
    final_kernel<<<B_, 256>>>(P1, P2, X, a2, graph_feature);
}

// round 4
// speedup vs baseline: 2.0079x; 1.6213x over previous
#include <cuda_runtime.h>
#include <cuda_bf16.h>
#include <cstdint>
#include <cstdio>

#define B_      1024
#define K_      11
#define L_KIN_  128
#define L_SUB_  64
#define L_STR_  128
#define D_SEQ_  1280
#define D_STR_  512
#define EMB_    1792        // D_SEQ + D_STR
#define EMB2_   2564        // 2*D_SEQ + 4
#define M_      (B_ * K_)   // 11264
#define NCHUNK_ 44

// ---------------- GEMM tile config ----------------
#define GBM 128
#define GBN 256
#define GBK 32
#define GSTAGES 3
#define GAS 36                      // A smem row stride (floats)
#define GBS 260                     // B smem row stride (floats)
#define GA_BUF (GBM * GAS)          // 4608
#define GB_BUF (GBK * GBS)          // 8320
#define GSMEM_FLOATS (GSTAGES * (GA_BUF + GB_BUF))   // 38784 -> 155136 B

// ---------------- scratch (device globals) ----------------
__device__ float g_X [(size_t)M_ * EMB2_];
__device__ float g_Y [(size_t)M_ * EMB2_];
__device__ float g_XA[(size_t)M_ * EMB2_];
__device__ float g_XB[(size_t)M_ * EMB2_];
__device__ float g_P1[(size_t)M_ * D_SEQ_];
__device__ float g_P2[(size_t)M_ * D_SEQ_];
__device__ float g_Wr[20936720];     // all 6 weight matrices, tf32-rounded
__device__ float g_kin[(size_t)B_ * D_SEQ_];
__device__ float g_psum[NCHUNK_ * EMB2_];
__device__ float g_psq [NCHUNK_ * EMB2_];
__device__ float g_ss  [8 * EMB2_];

__constant__ float c_props[21 * 4] = {
    0,0,0,0,  1,0,0,0,  0,0,0,0,  0,0,0,0,  1,0,0,0,  0,0,0,0,  0,0,0,0,
    1,0,0,0,  1,0,0,0,  0,0,0,0,  0,0,1,0,  0,0,0,0,  0,0,0,1,  0,0,1,0,
    1,0,0,0,  0,0,0,1,  0,1,0,0,  0,0,0,1,  0,1,0,0,  0,1,0,0,  0,0,0,0
};

__device__ __forceinline__ float tf32r(float x) {
    unsigned u;
    asm("cvt.rna.tf32.f32 %0, %1;" : "=r"(u) : "f"(x));
    return __uint_as_float(u);
}
__device__ __forceinline__ float sigmoidf_(float x) { return 1.f / (1.f + expf(-x)); }

__device__ __forceinline__ void mma_tf32(float* d, const unsigned* a, const unsigned* b) {
    asm volatile(
        "mma.sync.aligned.m16n8k8.row.col.f32.tf32.tf32.f32 "
        "{%0,%1,%2,%3}, {%4,%5,%6,%7}, {%8,%9}, {%0,%1,%2,%3};\n"
        : "+f"(d[0]), "+f"(d[1]), "+f"(d[2]), "+f"(d[3])
        : "r"(a[0]), "r"(a[1]), "r"(a[2]), "r"(a[3]), "r"(b[0]), "r"(b[1]));
}

__device__ __forceinline__ void cp16(unsigned dst, const void* src, bool pred) {
    int sz = pred ? 16 : 0;
    asm volatile("cp.async.cg.shared.global [%0], [%1], 16, %2;\n"
                 :: "r"(dst), "l"(src), "r"(sz));
}

// ---------------- kin mean ----------------
__global__ __launch_bounds__(256) void kin_mean_kernel(const float* __restrict__ kin_in,
                                                       float* __restrict__ kin_out) {
    int b = blockIdx.x;
    const float* base = kin_in + ((size_t)b * L_KIN_ + 1) * D_SEQ_;
    for (int i = threadIdx.x; i < D_SEQ_ / 4; i += blockDim.x) {
        float4 acc = make_float4(0.f, 0.f, 0.f, 0.f);
        #pragma unroll 4
        for (int r = 0; r < L_KIN_ - 1; ++r) {
            float4 v = *(const float4*)(base + (size_t)r * D_SEQ_ + i * 4);
            acc.x += v.x; acc.y += v.y; acc.z += v.z; acc.w += v.w;
        }
        const float inv = 1.f / 127.f;
        *(float4*)(kin_out + (size_t)b * D_SEQ_ + i * 4) =
            make_float4(acc.x * inv, acc.y * inv, acc.z * inv, acc.w * inv);
    }
}

// ---------------- build gfeat ----------------
__global__ __launch_bounds__(256) void build_gfeat_kernel(
    const float* __restrict__ sub, const float* __restrict__ n2,
    const float* __restrict__ phos, const int* __restrict__ position,
    float* __restrict__ X, float* __restrict__ node_feature) {
    int b = blockIdx.x, k = blockIdx.y;
    size_t m = (size_t)b * K_ + k;
    const float* src1 = sub + ((size_t)b * L_SUB_ + 1 + k) * D_SEQ_;
    float* dst = X + m * EMB_;
    float* nf  = node_feature + m * D_SEQ_;
    bool mid = (k == K_ / 2);
    for (int i = threadIdx.x; i < D_SEQ_ / 4; i += blockDim.x) {
        float4 v = *(const float4*)(src1 + i * 4);
        *(float4*)(nf + i * 4) = v;
        if (mid) {
            float4 p = *(const float4*)(phos + i * 4);
            v.x += p.x; v.y += p.y; v.z += p.z; v.w += p.w;
        }
        *(float4*)(dst + i * 4) = v;
    }
    int row = position[b] + k - K_ / 2;
    bool ok = (row >= 0 && row < L_STR_);
    const float* src2 = n2 + ((size_t)b * L_STR_ + (ok ? row : 0)) * D_STR_;
    for (int i = threadIdx.x; i < D_STR_ / 4; i += blockDim.x) {
        float4 v = make_float4(0.f, 0.f, 0.f, 0.f);
        if (ok) v = *(const float4*)(src2 + i * 4);
        if (mid) {
            float4 p = *(const float4*)(phos + D_SEQ_ + i * 4);
            v.x += p.x; v.y += p.y; v.z += p.z; v.w += p.w;
        }
        *(float4*)(dst + D_SEQ_ + i * 4) = v;
    }
}

// ---------------- column statistics ----------------
__global__ __launch_bounds__(256) void colstats_partial(
    const float* __restrict__ X, float* __restrict__ psum, float* __restrict__ psq,
    int ncols, int rows_per_chunk) {
    int col = blockIdx.x * blockDim.x + threadIdx.x;
    if (col >= ncols) return;
    int r0 = blockIdx.y * rows_per_chunk;
    float s = 0.f, q = 0.f;
    const float* p = X + (size_t)r0 * ncols + col;
    #pragma unroll 4
    for (int r = 0; r < rows_per_chunk; ++r, p += ncols) {
        float v = *p;
        s += v; q += v * v;
    }
    psum[blockIdx.y * ncols + col] = s;
    psq [blockIdx.y * ncols + col] = q;
}

__global__ __launch_bounds__(256) void finalize_stats(
    const float* __restrict__ psum, const float* __restrict__ psq, int ncols,
    const float* __restrict__ gA, const float* __restrict__ bA,
    const float* __restrict__ gB, const float* __restrict__ bB,
    float* __restrict__ sA, float* __restrict__ tA,
    float* __restrict__ sB, float* __restrict__ tB) {
    int col = blockIdx.x * blockDim.x + threadIdx.x;
    if (col >= ncols) return;
    float s = 0.f, q = 0.f;
    for (int c = 0; c < NCHUNK_; ++c) {
        s += psum[c * ncols + col];
        q += psq [c * ncols + col];
    }
    const float inv_n = 1.f / (float)M_;
    float mean = s * inv_n;
    float var  = q * inv_n - mean * mean;
    float inv  = rsqrtf(var + 1e-5f);
    float sa = gA[col] * inv; sA[col] = sa; tA[col] = bA[col] - mean * sa;
    float sb = gB[col] * inv; sB[col] = sb; tB[col] = bB[col] - mean * sb;
}

// ---------------- tf32 round-copy (weights) ----------------
__global__ __launch_bounds__(256) void roundcopy_kernel(const float* __restrict__ in,
                                                        float* __restrict__ out, int n4) {
    int i = blockIdx.x * blockDim.x + threadIdx.x;
    if (i >= n4) return;
    float4 v = *(const float4*)(in + i * 4);
    v.x = tf32r(v.x); v.y = tf32r(v.y); v.z = tf32r(v.z); v.w = tf32r(v.w);
    *(float4*)(out + i * 4) = v;
}

// ---------------- BN transform: XA = tf32r(relu(s1*x+t1)), XB = ... ----------------
__global__ __launch_bounds__(256) void bn_transform_kernel(
    const float* __restrict__ X,
    const float* __restrict__ s1, const float* __restrict__ t1,
    const float* __restrict__ s2, const float* __restrict__ t2,
    float* __restrict__ XA, float* __restrict__ XB, int ncols, int nrows) {
    size_t i = (size_t)blockIdx.x * blockDim.x + threadIdx.x;
    size_t total4 = (size_t)nrows * ncols / 4;
    if (i >= total4) return;
    int col = (int)((i * 4) % ncols);
    float4 v  = *(const float4*)(X + i * 4);
    float4 a1 = *(const float4*)(s1 + col);
    float4 b1 = *(const float4*)(t1 + col);
    float4 a2 = *(const float4*)(s2 + col);
    float4 b2 = *(const float4*)(t2 + col);
    float4 r1, r2;
    r1.x = tf32r(fmaxf(fmaf(v.x, a1.x, b1.x), 0.f));
    r1.y = tf32r(fmaxf(fmaf(v.y, a1.y, b1.y), 0.f));
    r1.z = tf32r(fmaxf(fmaf(v.z, a1.z, b1.z), 0.f));
    r1.w = tf32r(fmaxf(fmaf(v.w, a1.w, b1.w), 0.f));
    r2.x = tf32r(fmaxf(fmaf(v.x, a2.x, b2.x), 0.f));
    r2.y = tf32r(fmaxf(fmaf(v.y, a2.y, b2.y), 0.f));
    r2.z = tf32r(fmaxf(fmaf(v.z, a2.z, b2.z), 0.f));
    r2.w = tf32r(fmaxf(fmaf(v.w, a2.w, b2.w), 0.f));
    *(float4*)(XA + i * 4) = r1;
    *(float4*)(XB + i * 4) = r2;
}

// ---------------- pure tf32 GEMM: cp.async multistage, 128x256x32 ----------------
// C = A @ W + bias ; relu_out: C = tf32r(relu(C))
__global__ __launch_bounds__(256, 1) void gemm_tf32_ms(
    const float* __restrict__ A, const float* __restrict__ W,
    const float* __restrict__ bias, float* __restrict__ C,
    int Kd, int N, int relu_out) {
    extern __shared__ float smem[];
    float* sA = smem;
    float* sB = smem + GSTAGES * GA_BUF;
    const unsigned sA_u = (unsigned)__cvta_generic_to_shared(sA);
    const unsigned sB_u = (unsigned)__cvta_generic_to_shared(sB);

    const int tid  = threadIdx.x;
    const int bm   = blockIdx.y * GBM;
    const int bn   = blockIdx.x * GBN;
    const int warp = tid >> 5, lane = tid & 31;
    const int wm = (warp & 1) << 6;     // 0,64
    const int wn = (warp >> 1) << 6;    // 0,64,128,192
    const int g  = lane >> 2, tg = lane & 3;

    const int ktiles = (Kd + GBK - 1) / GBK;

    float acc[4][8][4];
    #pragma unroll
    for (int mt = 0; mt < 4; ++mt)
        #pragma unroll
        for (int nt = 0; nt < 8; ++nt)
            #pragma unroll
            for (int i = 0; i < 4; ++i) acc[mt][nt][i] = 0.f;

    // ---- async load of one stage ----
    auto load_stage = [&](int kt, int buf) {
        const int k0 = kt * GBK;
        unsigned sab = sA_u + (unsigned)(buf * GA_BUF) * 4u;
        #pragma unroll
        for (int it = 0; it < 4; ++it) {
            int idx = tid + it * 256;
            int row = idx >> 3, seg = (idx & 7) << 2;
            int gk = k0 + seg;
            bool p = (gk < Kd);
            const float* src = A + (size_t)(bm + row) * Kd + (p ? gk : 0);
            cp16(sab + (unsigned)(row * GAS + seg) * 4u, src, p);
        }
        unsigned sbb = sB_u + (unsigned)(buf * GB_BUF) * 4u;
        #pragma unroll
        for (int it = 0; it < 8; ++it) {
            int idx = tid + it * 256;
            int row = idx >> 6, seg = (idx & 63) << 2;
            int gk = k0 + row, gc = bn + seg;
            bool p = (gk < Kd) && (gc < N);
            const float* src = W + (p ? ((size_t)gk * N + gc) : 0);
            cp16(sbb + (unsigned)(row * GBS + seg) * 4u, src, p);
        }
        asm volatile("cp.async.commit_group;\n");
    };

    auto compute = [&](int buf) {
        const float* pA = sA + buf * GA_BUF;
        const float* pB = sB + buf * GB_BUF;
        #pragma unroll
        for (int kk = 0; kk < 4; ++kk) {
            const int kb = kk << 3;
            unsigned af[4][4], bf[8][2];
            #pragma unroll
            for (int mt = 0; mt < 4; ++mt) {
                int r = wm + (mt << 4);
                af[mt][0] = __float_as_uint(pA[(r + g) * GAS + kb + tg]);
                af[mt][1] = __float_as_uint(pA[(r + g + 8) * GAS + kb + tg]);
                af[mt][2] = __float_as_uint(pA[(r + g) * GAS + kb + tg + 4]);
                af[mt][3] = __float_as_uint(pA[(r + g + 8) * GAS + kb + tg + 4]);
            }
            #pragma unroll
            for (int nt = 0; nt < 8; ++nt) {
                int c = wn + (nt << 3) + g;
                bf[nt][0] = __float_as_uint(pB[(kb + tg) * GBS + c]);
                bf[nt][1] = __float_as_uint(pB[(kb + tg + 4) * GBS + c]);
            }
            #pragma unroll
            for (int mt = 0; mt < 4; ++mt)
                #pragma unroll
                for (int nt = 0; nt < 8; ++nt)
                    mma_tf32(acc[mt][nt], af[mt], bf[nt]);
        }
    };

    // ---- prologue: fill GSTAGES-1 stages ----
    #pragma unroll
    for (int s = 0; s < GSTAGES - 1; ++s) load_stage(s, s);

    // ---- main loop: one barrier per slab ----
    for (int kt = 0; kt < ktiles; ++kt) {
        asm volatile("cp.async.wait_group %0;\n" :: "n"(GSTAGES - 2));
        __syncthreads();
        int nxt = kt + GSTAGES - 1;
        if (nxt < ktiles) load_stage(nxt, nxt % GSTAGES);
        else asm volatile("cp.async.commit_group;\n");
        compute(kt % GSTAGES);
    }

    // ---- epilogue ----
    #pragma unroll
    for (int mt = 0; mt < 4; ++mt) {
        int r = bm + wm + (mt << 4);
        #pragma unroll
        for (int nt = 0; nt < 8; ++nt) {
            int c = bn + wn + (nt << 3) + (tg << 1);
            if (c < N) {
                float b0 = bias[c], b1 = bias[c + 1];
                float v00 = acc[mt][nt][0] + b0, v01 = acc[mt][nt][1] + b1;
                float v10 = acc[mt][nt][2] + b0, v11 = acc[mt][nt][3] + b1;
                if (relu_out) {
                    v00 = tf32r(fmaxf(v00, 0.f)); v01 = tf32r(fmaxf(v01, 0.f));
                    v10 = tf32r(fmaxf(v10, 0.f)); v11 = tf32r(fmaxf(v11, 0.f));
                }
                C[(size_t)(r + g) * N + c]         = v00;
                C[(size_t)(r + g) * N + c + 1]     = v01;
                C[(size_t)(r + g + 8) * N + c]     = v10;
                C[(size_t)(r + g + 8) * N + c + 1] = v11;
            }
        }
    }
}

// ---------------- combine stage 1 -> gfeat2 ----------------
__global__ __launch_bounds__(256) void combine1_kernel(
    const float* __restrict__ F1, const float* __restrict__ F2,
    const float* __restrict__ nf, const float* __restrict__ kin,
    const float* __restrict__ a, const int* __restrict__ raw_seq,
    float* __restrict__ X2) {
    int b = blockIdx.x, k = blockIdx.y;
    size_t m = (size_t)b * K_ + k;
    float a0 = a[0], a1 = a[1];
    const float* f1 = F1 + m * D_SEQ_;
    const float* f2 = F2 + m * D_SEQ_;
    const float* g1 = nf + m * D_SEQ_;
    const float* kb = kin + (size_t)b * D_SEQ_;
    float* dst = X2 + m * EMB2_;
    for (int i = threadIdx.x; i < D_SEQ_ / 4; i += blockDim.x) {
        float4 v1 = *(const float4*)(f1 + i * 4);
        float4 v2 = *(const float4*)(f2 + i * 4);
        float4 vg = *(const float4*)(g1 + i * 4);
        float4 r;
        r.x = sigmoidf_(v1.x) * vg.x * a0 + v2.x * a1;
        r.y = sigmoidf_(v1.y) * vg.y * a0 + v2.y * a1;
        r.z = sigmoidf_(v1.z) * vg.z * a0 + v2.z * a1;
        r.w = sigmoidf_(v1.w) * vg.w * a0 + v2.w * a1;
        *(float4*)(dst + i * 4) = r;
        *(float4*)(dst + D_SEQ_ + i * 4) = *(const float4*)(kb + i * 4);
    }
    if (threadIdx.x < 4) {
        int sid = raw_seq[m];
        dst[2 * D_SEQ_ + threadIdx.x] = c_props[sid * 4 + threadIdx.x];
    }
}

// ---------------- final combine + K-reduce ----------------
__global__ __launch_bounds__(256) void final_kernel(
    const float* __restrict__ G1, const float* __restrict__ G2,
    const float* __restrict__ X2, const float* __restrict__ a2,
    float* __restrict__ out) {
    int b = blockIdx.x;
    float s0 = a2[0], s1 = a2[1];
    for (int i = threadIdx.x; i < D_SEQ_ / 4; i += blockDim.x) {
        float4 acc = make_float4(0.f, 0.f, 0.f, 0.f);
        for (int k = 0; k < K_; ++k) {
            size_t m = (size_t)b * K_ + k;
            float4 f1 = *(const float4*)(G1 + m * D_SEQ_ + i * 4);
            float4 f2 = *(const float4*)(G2 + m * D_SEQ_ + i * 4);
            float4 gn = *(const float4*)(X2 + m * EMB2_ + i * 4);
            acc.x += sigmoidf_(f1.x) * gn.x * s0 + f2.x * s1;
            acc.y += sigmoidf_(f1.y) * gn.y * s0 + f2.y * s1;
            acc.z += sigmoidf_(f1.z) * gn.z * s0 + f2.z * s1;
            acc.w += sigmoidf_(f1.w) * gn.w * s0 + f2.w * s1;
        }
        *(float4*)(out + (size_t)b * D_SEQ_ + i * 4) = acc;
    }
}

// ---------------- launch ----------------
extern "C" void kernel_launch(void* const* d_in, const int* in_sizes, int n_in,
                              void* d_out, int out_size) {
    const float* kin_in   = (const float*)d_in[0];
    const float* sub      = (const float*)d_in[1];
    const float* n2       = (const float*)d_in[2];
    const float* a        = (const float*)d_in[4];
    const float* a2       = (const float*)d_in[5];
    const float* phos     = (const float*)d_in[6];
    const float* g1_gamma = (const float*)d_in[7];
    const float* g1_beta  = (const float*)d_in[8];
    const float* g1_W     = (const float*)d_in[9];
    const float* g1_b     = (const float*)d_in[10];
    const float* r1_gamma = (const float*)d_in[11];
    const float* r1_beta  = (const float*)d_in[12];
    const float* r1_W1    = (const float*)d_in[13];
    const float* r1_b1    = (const float*)d_in[14];
    const float* r1_W2    = (const float*)d_in[15];
    const float* r1_b2    = (const float*)d_in[16];
    const float* g2_gamma = (const float*)d_in[17];
    const float* g2_beta  = (const float*)d_in[18];
    const float* g2_W     = (const float*)d_in[19];
    const float* g2_b     = (const float*)d_in[20];
    const float* r2_gamma = (const float*)d_in[21];
    const float* r2_beta  = (const float*)d_in[22];
    const float* r2_W1    = (const float*)d_in[23];
    const float* r2_b1    = (const float*)d_in[24];
    const float* r2_W2    = (const float*)d_in[25];
    const float* r2_b2    = (const float*)d_in[26];
    const int*   position = (const int*)d_in[27];
    const int*   raw_seq  = (const int*)d_in[28];

    float* out = (float*)d_out;
    float* graph_feature = out;
    float* node_feature  = out + (size_t)B_ * D_SEQ_;

    float *X, *Y, *XA, *XB, *P1, *P2, *Wr, *kin, *psum, *psq, *ss;
    cudaGetSymbolAddress((void**)&X,    g_X);
    cudaGetSymbolAddress((void**)&Y,    g_Y);
    cudaGetSymbolAddress((void**)&XA,   g_XA);
    cudaGetSymbolAddress((void**)&XB,   g_XB);
    cudaGetSymbolAddress((void**)&P1,   g_P1);
    cudaGetSymbolAddress((void**)&P2,   g_P2);
    cudaGetSymbolAddress((void**)&Wr,   g_Wr);
    cudaGetSymbolAddress((void**)&kin,  g_kin);
    cudaGetSymbolAddress((void**)&psum, g_psum);
    cudaGetSymbolAddress((void**)&psq,  g_psq);
    cudaGetSymbolAddress((void**)&ss,   g_ss);

    const int smem_bytes = GSMEM_FLOATS * (int)sizeof(float);   // 155136
    cudaFuncSetAttribute(gemm_tf32_ms,
                         cudaFuncAttributeMaxDynamicSharedMemorySize, smem_bytes);

    float* s_g1 = ss + 0 * EMB2_;  float* t_g1 = ss + 1 * EMB2_;
    float* s_r1 = ss + 2 * EMB2_;  float* t_r1 = ss + 3 * EMB2_;
    float* s_g2 = ss + 4 * EMB2_;  float* t_g2 = ss + 5 * EMB2_;
    float* s_r2 = ss + 6 * EMB2_;  float* t_r2 = ss + 7 * EMB2_;

    // pre-rounded weight offsets
    const int n_g1W  = EMB_  * D_SEQ_;   // 2293760
    const int n_r1W1 = EMB_  * EMB_;     // 3211264
    const int n_r1W2 = EMB_  * D_SEQ_;
    const int n_g2W  = EMB2_ * D_SEQ_;   // 3281920
    const int n_r2W1 = EMB2_ * EMB2_;    // 6574096
    float* W_g1  = Wr;
    float* W_r11 = W_g1  + n_g1W;
    float* W_r12 = W_r11 + n_r1W1;
    float* W_g2  = W_r12 + n_r1W2;
    float* W_r21 = W_g2  + n_g2W;
    float* W_r22 = W_r21 + n_r2W1;

    // 0. round weights to tf32 (RNA) once per launch
    auto rc = [&](const float* src, float* dst, int n) {
        roundcopy_kernel<<<(n / 4 + 255) / 256, 256>>>(src, dst, n / 4);
    };
    rc(g1_W,  W_g1,  n_g1W);
    rc(r1_W1, W_r11, n_r1W1);
    rc(r1_W2, W_r12, n_r1W2);
    rc(g2_W,  W_g2,  n_g2W);
    rc(r2_W1, W_r21, n_r2W1);
    rc(r2_W2, W_r22, EMB2_ * D_SEQ_);

    // 1. kin mean
    kin_mean_kernel<<<B_, 256>>>(kin_in, kin);

    // 2. build gfeat
    build_gfeat_kernel<<<dim3(B_, K_), 256>>>(sub, n2, phos, position, X, node_feature);

    // 3. BN stats stage 1
    colstats_partial<<<dim3((EMB_ + 255) / 256, NCHUNK_), 256>>>(X, psum, psq, EMB_, M_ / NCHUNK_);
    finalize_stats<<<(EMB_ + 255) / 256, 256>>>(psum, psq, EMB_,
        g1_gamma, g1_beta, r1_gamma, r1_beta, s_g1, t_g1, s_r1, t_r1);

    // 4. transforms
    {
        size_t total4 = (size_t)M_ * EMB_ / 4;
        bn_transform_kernel<<<(int)((total4 + 255) / 256), 256>>>(
            X, s_g1, t_g1, s_r1, t_r1, XA, XB, EMB_, M_);
    }

    // 5-7. stage-1 GEMMs (pure)
    gemm_tf32_ms<<<dim3(D_SEQ_ / GBN, M_ / GBM), 256, smem_bytes>>>(XA, W_g1,  g1_b,  P1, EMB_, D_SEQ_, 0);
    gemm_tf32_ms<<<dim3(EMB_  / GBN, M_ / GBM), 256, smem_bytes>>>(XB, W_r11, r1_b1, Y,  EMB_, EMB_,  1);
    gemm_tf32_ms<<<dim3(D_SEQ_ / GBN, M_ / GBM), 256, smem_bytes>>>(Y,  W_r12, r1_b2, P2, EMB_, D_SEQ_, 0);

    // 8. combine -> gfeat2
    combine1_kernel<<<dim3(B_, K_), 256>>>(P1, P2, node_feature, kin, a, raw_seq, X);

    // 9. BN stats stage 2
    colstats_partial<<<dim3((EMB2_ + 255) / 256, NCHUNK_), 256>>>(X, psum, psq, EMB2_, M_ / NCHUNK_);
    finalize_stats<<<(EMB2_ + 255) / 256, 256>>>(psum, psq, EMB2_,
        g2_gamma, g2_beta, r2_gamma, r2_beta, s_g2, t_g2, s_r2, t_r2);

    // 10. transforms stage 2
    {
        size_t total4 = (size_t)M_ * EMB2_ / 4;
        bn_transform_kernel<<<(int)((total4 + 255) / 256), 256>>>(
            X, s_g2, t_g2, s_r2, t_r2, XA, XB, EMB2_, M_);
    }

    // 11-13. stage-2 GEMMs
    gemm_tf32_ms<<<dim3(D_SEQ_ / GBN, M_ / GBM), 256, smem_bytes>>>(XA, W_g2,  g2_b,  P1, EMB2_, D_SEQ_, 0);
    gemm_tf32_ms<<<dim3((EMB2_ + GBN - 1) / GBN, M_ / GBM), 256, smem_bytes>>>(XB, W_r21, r2_b1, Y, EMB2_, EMB2_, 1);
    gemm_tf32_ms<<<dim3(D_SEQ_ / GBN, M_ / GBM), 256, smem_bytes>>>(Y,  W_r22, r2_b2, P2, EMB2_, D_SEQ_, 0);

    // 14. final combine + K-reduce
    final_kernel<<<B_, 256>>>(P1, P2, X, a2, graph_feature);
}